// round 1
// baseline (speedup 1.0000x reference)
#include <cuda_runtime.h>

#define MAXN 20000
#define MAXE 320000
#define MAXEP (MAXN + MAXE)

// ---------------- scratch (no allocs allowed) ----------------
__device__ int   g_deg[MAXN];
__device__ int   g_row[MAXN + 1];
__device__ int   g_cur[MAXN];
__device__ int   g_eid[MAXEP];
__device__ int   g_src[MAXEP];
__device__ float g_dis[MAXN];
__device__ __align__(16) float g_als[MAXN * 4];
__device__ __align__(16) float g_ald[MAXN * 4];
__device__ __align__(16) float g_bufA[MAXN * 256];
__device__ __align__(16) float g_bufB[MAXN * 256];
__device__ __align__(16) float g_bufC[MAXN * 256];

// ---------------- CSR build ----------------
__global__ void k_zero(int n) {
    int i = blockIdx.x * blockDim.x + threadIdx.x;
    if (i < n) g_deg[i] = 0;
}

__global__ void k_count(const int* __restrict__ ei, int E, int EP) {
    int i = blockIdx.x * blockDim.x + threadIdx.x;
    if (i < EP) {
        int d = (i < E) ? ei[E + i] : (i - E);
        atomicAdd(&g_deg[d], 1);
    }
}

// single-block inclusive scan over N (<= 20480 handled by loop)
__global__ void k_scan(int n) {
    __shared__ int sh[1024];
    __shared__ int carry_s;
    int tid = threadIdx.x;
    if (tid == 0) { carry_s = 0; g_row[0] = 0; }
    __syncthreads();
    for (int base = 0; base < n; base += 1024) {
        int i = base + tid;
        int v = (i < n) ? g_deg[i] : 0;
        sh[tid] = v;
        __syncthreads();
        for (int off = 1; off < 1024; off <<= 1) {
            int t = (tid >= off) ? sh[tid - off] : 0;
            __syncthreads();
            sh[tid] += t;
            __syncthreads();
        }
        int incl = sh[tid];
        int c = carry_s;
        if (i < n) {
            g_row[i + 1] = c + incl;
            g_cur[i]     = c + incl - v;   // exclusive
            g_dis[i]     = rsqrtf((float)v);  // deg >= 1 (self loop)
        }
        __syncthreads();
        if (tid == 1023) carry_s = c + incl;
        __syncthreads();
    }
}

__global__ void k_scatter(const int* __restrict__ ei, int E, int EP) {
    int i = blockIdx.x * blockDim.x + threadIdx.x;
    if (i < EP) {
        int d = (i < E) ? ei[E + i] : (i - E);
        int pos = atomicAdd(&g_cur[d], 1);
        g_eid[pos] = i;
    }
}

// deterministic order: sort each row's edge ids ascending
__global__ void k_sort(int n) {
    int i = blockIdx.x * blockDim.x + threadIdx.x;
    if (i >= n) return;
    int r0 = g_row[i], r1 = g_row[i + 1];
    for (int a = r0 + 1; a < r1; a++) {
        int v = g_eid[a];
        int b = a - 1;
        while (b >= r0 && g_eid[b] > v) { g_eid[b + 1] = g_eid[b]; b--; }
        g_eid[b + 1] = v;
    }
}

__global__ void k_fill_src(const int* __restrict__ ei, int E, int EP) {
    int i = blockIdx.x * blockDim.x + threadIdx.x;
    if (i < EP) {
        int eid = g_eid[i];
        g_src[i] = (eid < E) ? ei[eid] : (eid - E);
    }
}

// ---------------- GEMMs ----------------
// C[M,256] = A[M,K] @ W[K,256], K multiple of 32
__global__ __launch_bounds__(256) void k_gemm256(const float* __restrict__ A,
                                                 const float* __restrict__ W,
                                                 float* __restrict__ C, int M, int K) {
    __shared__ float Ash[64][36];
    __shared__ float Wsh[32][256];
    int tid = threadIdx.x;
    int x = tid & 31, y = tid >> 5;
    int row0 = blockIdx.x * 64;
    float acc[8][8];
#pragma unroll
    for (int i = 0; i < 8; i++)
#pragma unroll
        for (int j = 0; j < 8; j++) acc[i][j] = 0.f;

    for (int k0 = 0; k0 < K; k0 += 32) {
#pragma unroll
        for (int t = 0; t < 2; t++) {
            int idx = tid + t * 256;
            int r = idx >> 3, kq = idx & 7;
            int grow = row0 + r;
            float4 v = make_float4(0.f, 0.f, 0.f, 0.f);
            if (grow < M) v = *(const float4*)(A + (size_t)grow * K + k0 + kq * 4);
            *(float4*)&Ash[r][kq * 4] = v;
        }
#pragma unroll
        for (int t = 0; t < 8; t++) {
            int idx = tid + t * 256;
            int kr = idx >> 6, cq = idx & 63;
            *(float4*)&Wsh[kr][cq * 4] = *(const float4*)(W + (size_t)(k0 + kr) * 256 + cq * 4);
        }
        __syncthreads();
#pragma unroll
        for (int k = 0; k < 32; k++) {
            float a[8];
#pragma unroll
            for (int i = 0; i < 8; i++) a[i] = Ash[y + 8 * i][k];
            float4 w0 = *(float4*)&Wsh[k][x * 4];
            float4 w1 = *(float4*)&Wsh[k][x * 4 + 128];
#pragma unroll
            for (int i = 0; i < 8; i++) {
                acc[i][0] += a[i] * w0.x; acc[i][1] += a[i] * w0.y;
                acc[i][2] += a[i] * w0.z; acc[i][3] += a[i] * w0.w;
                acc[i][4] += a[i] * w1.x; acc[i][5] += a[i] * w1.y;
                acc[i][6] += a[i] * w1.z; acc[i][7] += a[i] * w1.w;
            }
        }
        __syncthreads();
    }
#pragma unroll
    for (int i = 0; i < 8; i++) {
        int r = row0 + y + 8 * i;
        if (r < M) {
            *(float4*)(C + (size_t)r * 256 + x * 4) =
                make_float4(acc[i][0], acc[i][1], acc[i][2], acc[i][3]);
            *(float4*)(C + (size_t)r * 256 + x * 4 + 128) =
                make_float4(acc[i][4], acc[i][5], acc[i][6], acc[i][7]);
        }
    }
}

// C[M,64] = A[M,K] @ W[K,64], K multiple of 32
__global__ __launch_bounds__(256) void k_gemm64(const float* __restrict__ A,
                                                const float* __restrict__ W,
                                                float* __restrict__ C, int M, int K) {
    __shared__ float Ash[64][36];
    __shared__ float Wsh[32][64];
    int tid = threadIdx.x;
    int x = tid & 15, y = tid >> 4;
    int row0 = blockIdx.x * 64;
    float acc[4][4];
#pragma unroll
    for (int i = 0; i < 4; i++)
#pragma unroll
        for (int j = 0; j < 4; j++) acc[i][j] = 0.f;

    for (int k0 = 0; k0 < K; k0 += 32) {
#pragma unroll
        for (int t = 0; t < 2; t++) {
            int idx = tid + t * 256;
            int r = idx >> 3, kq = idx & 7;
            int grow = row0 + r;
            float4 v = make_float4(0.f, 0.f, 0.f, 0.f);
            if (grow < M) v = *(const float4*)(A + (size_t)grow * K + k0 + kq * 4);
            *(float4*)&Ash[r][kq * 4] = v;
        }
#pragma unroll
        for (int t = 0; t < 2; t++) {
            int idx = tid + t * 256;
            int kr = idx >> 4, cq = idx & 15;
            *(float4*)&Wsh[kr][cq * 4] = *(const float4*)(W + (size_t)(k0 + kr) * 64 + cq * 4);
        }
        __syncthreads();
#pragma unroll
        for (int k = 0; k < 32; k++) {
            float a[4];
#pragma unroll
            for (int i = 0; i < 4; i++) a[i] = Ash[y + 16 * i][k];
            float4 w = *(float4*)&Wsh[k][x * 4];
#pragma unroll
            for (int i = 0; i < 4; i++) {
                acc[i][0] += a[i] * w.x; acc[i][1] += a[i] * w.y;
                acc[i][2] += a[i] * w.z; acc[i][3] += a[i] * w.w;
            }
        }
        __syncthreads();
    }
#pragma unroll
    for (int i = 0; i < 4; i++) {
        int r = row0 + y + 16 * i;
        if (r < M)
            *(float4*)(C + (size_t)r * 64 + x * 4) =
                make_float4(acc[i][0], acc[i][1], acc[i][2], acc[i][3]);
    }
}

// ---------------- GCN aggregate (warp per node) ----------------
__global__ void k_gcn_agg(const float* __restrict__ xw, const float* __restrict__ bias,
                          float* __restrict__ out, int n) {
    int w = (blockIdx.x * blockDim.x + threadIdx.x) >> 5;
    int lane = threadIdx.x & 31;
    if (w >= n) return;
    int r0 = g_row[w], r1 = g_row[w + 1];
    float acc0 = 0.f, acc1 = 0.f;
    for (int e = r0; e < r1; e++) {
        int s = g_src[e];
        float sc = g_dis[s];
        const float* xs = xw + (size_t)s * 64;
        acc0 += sc * xs[lane];
        acc1 += sc * xs[32 + lane];
    }
    float di = g_dis[w];
    float v0 = di * acc0 + bias[lane];
    float v1 = di * acc1 + bias[32 + lane];
    out[(size_t)w * 64 + lane]      = fmaxf(v0, 0.f);
    out[(size_t)w * 64 + 32 + lane] = fmaxf(v1, 0.f);
}

// ---------------- attention prep: per-node a_src.x, a_dst.x ----------------
__global__ void k_prep(const float* __restrict__ xw, const float* __restrict__ asrc,
                       const float* __restrict__ adst, int n) {
    int w = (blockIdx.x * blockDim.x + threadIdx.x) >> 5;
    int lane = threadIdx.x & 31;
    if (w >= n) return;
    const float4* xv = (const float4*)(xw + (size_t)w * 256);
    float4 x0 = xv[lane * 2], x1 = xv[lane * 2 + 1];
    const float4* sv = (const float4*)asrc;
    const float4* dv = (const float4*)adst;
    float4 a0 = sv[lane * 2], a1 = sv[lane * 2 + 1];
    float4 b0 = dv[lane * 2], b1 = dv[lane * 2 + 1];
    float ss = x0.x * a0.x + x0.y * a0.y + x0.z * a0.z + x0.w * a0.w
             + x1.x * a1.x + x1.y * a1.y + x1.z * a1.z + x1.w * a1.w;
    float dd = x0.x * b0.x + x0.y * b0.y + x0.z * b0.z + x0.w * b0.w
             + x1.x * b1.x + x1.y * b1.y + x1.z * b1.z + x1.w * b1.w;
#pragma unroll
    for (int d = 4; d; d >>= 1) {
        ss += __shfl_down_sync(0xffffffffu, ss, d);
        dd += __shfl_down_sync(0xffffffffu, dd, d);
    }
    if ((lane & 7) == 0) {
        int h = lane >> 3;
        g_als[(size_t)w * 4 + h] = ss;
        g_ald[(size_t)w * 4 + h] = dd;
    }
}

// ---------------- GAT aggregate (warp per node, all 4 heads) ----------------
// MODE 0: concat(256) + bias(256) + relu ; MODE 1: head-mean(64) + bias + relu ;
// MODE 2: head-mean(64) + bias, no relu
template <int MODE>
__global__ void k_gat_agg(const float* __restrict__ xw, const float* __restrict__ bias,
                          float* __restrict__ alpha, float* __restrict__ out, int n) {
    int w = (blockIdx.x * blockDim.x + threadIdx.x) >> 5;
    int lane = threadIdx.x & 31;
    if (w >= n) return;
    int r0 = g_row[w], r1 = g_row[w + 1];
    float4 ad = *(const float4*)&g_ald[(size_t)w * 4];

    // pass 1: exact max per head
    float m0 = -3e38f, m1 = -3e38f, m2 = -3e38f, m3 = -3e38f;
    for (int e = r0 + lane; e < r1; e += 32) {
        int s = g_src[e];
        float4 as4 = *(const float4*)&g_als[(size_t)s * 4];
        float v0 = as4.x + ad.x; v0 = v0 > 0.f ? v0 : 0.2f * v0;
        float v1 = as4.y + ad.y; v1 = v1 > 0.f ? v1 : 0.2f * v1;
        float v2 = as4.z + ad.z; v2 = v2 > 0.f ? v2 : 0.2f * v2;
        float v3 = as4.w + ad.w; v3 = v3 > 0.f ? v3 : 0.2f * v3;
        m0 = fmaxf(m0, v0); m1 = fmaxf(m1, v1); m2 = fmaxf(m2, v2); m3 = fmaxf(m3, v3);
    }
#pragma unroll
    for (int d = 16; d; d >>= 1) {
        m0 = fmaxf(m0, __shfl_xor_sync(0xffffffffu, m0, d));
        m1 = fmaxf(m1, __shfl_xor_sync(0xffffffffu, m1, d));
        m2 = fmaxf(m2, __shfl_xor_sync(0xffffffffu, m2, d));
        m3 = fmaxf(m3, __shfl_xor_sync(0xffffffffu, m3, d));
    }

    // pass 2: sum of exp; stash unnormalized p in alpha slot
    float s0 = 0.f, s1 = 0.f, s2 = 0.f, s3 = 0.f;
    for (int e = r0 + lane; e < r1; e += 32) {
        int eid = g_eid[e];
        int s = g_src[e];
        float4 as4 = *(const float4*)&g_als[(size_t)s * 4];
        float v0 = as4.x + ad.x; v0 = v0 > 0.f ? v0 : 0.2f * v0;
        float v1 = as4.y + ad.y; v1 = v1 > 0.f ? v1 : 0.2f * v1;
        float v2 = as4.z + ad.z; v2 = v2 > 0.f ? v2 : 0.2f * v2;
        float v3 = as4.w + ad.w; v3 = v3 > 0.f ? v3 : 0.2f * v3;
        float p0 = __expf(v0 - m0), p1 = __expf(v1 - m1);
        float p2 = __expf(v2 - m2), p3 = __expf(v3 - m3);
        s0 += p0; s1 += p1; s2 += p2; s3 += p3;
        *(float4*)&alpha[(size_t)eid * 4] = make_float4(p0, p1, p2, p3);
    }
#pragma unroll
    for (int d = 16; d; d >>= 1) {
        s0 += __shfl_xor_sync(0xffffffffu, s0, d);
        s1 += __shfl_xor_sync(0xffffffffu, s1, d);
        s2 += __shfl_xor_sync(0xffffffffu, s2, d);
        s3 += __shfl_xor_sync(0xffffffffu, s3, d);
    }
    float i0 = 1.f / (s0 + 1e-16f), i1 = 1.f / (s1 + 1e-16f);
    float i2 = 1.f / (s2 + 1e-16f), i3 = 1.f / (s3 + 1e-16f);
    __syncwarp();

    // pass 3: normalize alpha in place + aggregate 256 channels
    float acc[8] = {0.f, 0.f, 0.f, 0.f, 0.f, 0.f, 0.f, 0.f};
    for (int e = r0; e < r1; e++) {
        int eid = g_eid[e];
        int s = g_src[e];
        float4 p = *(const float4*)&alpha[(size_t)eid * 4];
        float a0 = p.x * i0, a1 = p.y * i1, a2 = p.z * i2, a3 = p.w * i3;
        if (lane < 4) {
            float av = (lane == 0) ? a0 : (lane == 1) ? a1 : (lane == 2) ? a2 : a3;
            alpha[(size_t)eid * 4 + lane] = av;
        }
        const float* xs = xw + (size_t)s * 256;
        acc[0] += a0 * xs[lane];        acc[1] += a0 * xs[32 + lane];
        acc[2] += a1 * xs[64 + lane];   acc[3] += a1 * xs[96 + lane];
        acc[4] += a2 * xs[128 + lane];  acc[5] += a2 * xs[160 + lane];
        acc[6] += a3 * xs[192 + lane];  acc[7] += a3 * xs[224 + lane];
    }

    if (MODE == 0) {
#pragma unroll
        for (int k = 0; k < 8; k++) {
            int c = k * 32 + lane;
            out[(size_t)w * 256 + c] = fmaxf(acc[k] + bias[c], 0.f);
        }
    } else {
        float u0 = (acc[0] + acc[2] + acc[4] + acc[6]) * 0.25f + bias[lane];
        float u1 = (acc[1] + acc[3] + acc[5] + acc[7]) * 0.25f + bias[32 + lane];
        if (MODE == 1) { u0 = fmaxf(u0, 0.f); u1 = fmaxf(u1, 0.f); }
        out[(size_t)w * 64 + lane]      = u0;
        out[(size_t)w * 64 + 32 + lane] = u1;
    }
}

// ---------------- host ----------------
extern "C" void kernel_launch(void* const* d_in, const int* in_sizes, int n_in,
                              void* d_out, int out_size) {
    int n  = in_sizes[0] / 128;
    int E  = in_sizes[1] / 2;
    int EP = E + n;

    const float* x         = (const float*)d_in[0];
    const int*   ei        = (const int*)d_in[1];
    const float* gcn_W     = (const float*)d_in[2];
    const float* gcn_b     = (const float*)d_in[3];
    const float* gat1_W    = (const float*)d_in[4];
    const float* gat1_asrc = (const float*)d_in[5];
    const float* gat1_adst = (const float*)d_in[6];
    const float* gat1_b    = (const float*)d_in[7];
    const float* gat2_W    = (const float*)d_in[8];
    const float* gat2_asrc = (const float*)d_in[9];
    const float* gat2_adst = (const float*)d_in[10];
    const float* gat2_b    = (const float*)d_in[11];
    const float* mean_W    = (const float*)d_in[12];
    const float* mean_asrc = (const float*)d_in[13];
    const float* mean_adst = (const float*)d_in[14];
    const float* mean_b    = (const float*)d_in[15];
    const float* std_W     = (const float*)d_in[16];
    const float* std_asrc  = (const float*)d_in[17];
    const float* std_adst  = (const float*)d_in[18];
    const float* std_b     = (const float*)d_in[19];

    float* out    = (float*)d_out;
    float* z_mean = out;
    float* z_std  = out + (size_t)n * 64;
    float* a1     = out + (size_t)2 * n * 64;
    float* a2     = a1 + (size_t)EP * 4;
    float* am     = a2 + (size_t)EP * 4;
    float* as_    = am + (size_t)EP * 4;

    float *bufA, *bufB, *bufC;
    cudaGetSymbolAddress((void**)&bufA, g_bufA);
    cudaGetSymbolAddress((void**)&bufB, g_bufB);
    cudaGetSymbolAddress((void**)&bufC, g_bufC);

    int gN   = (n + 255) / 256;
    int gEP  = (EP + 255) / 256;
    int gW   = (n + 7) / 8;        // warp-per-node kernels, 256 threads
    int gG   = (n + 63) / 64;      // GEMM row blocks

    // CSR build (deterministic: rows sorted by edge id)
    k_zero<<<gN, 256>>>(n);
    k_count<<<gEP, 256>>>(ei, E, EP);
    k_scan<<<1, 1024>>>(n);
    k_scatter<<<gEP, 256>>>(ei, E, EP);
    k_sort<<<(n + 127) / 128, 128>>>(n);
    k_fill_src<<<gEP, 256>>>(ei, E, EP);

    // layer 0: GCN
    k_gemm64<<<gG, 256>>>(x, gcn_W, bufA, n, 128);
    k_gcn_agg<<<gW, 256>>>(bufA, gcn_b, bufB, n);          // h0 -> bufB [N,64]

    // layer 1: GAT concat
    k_gemm256<<<gG, 256>>>(bufB, gat1_W, bufA, n, 64);     // xw1 -> bufA [N,256]
    k_prep<<<gW, 256>>>(bufA, gat1_asrc, gat1_adst, n);
    k_gat_agg<0><<<gW, 256>>>(bufA, gat1_b, a1, bufC, n);  // h1 -> bufC [N,256]

    // layer 2: GAT mean + relu
    k_gemm256<<<gG, 256>>>(bufC, gat2_W, bufA, n, 256);    // xw2 -> bufA
    k_prep<<<gW, 256>>>(bufA, gat2_asrc, gat2_adst, n);
    k_gat_agg<1><<<gW, 256>>>(bufA, gat2_b, a2, bufB, n);  // h2 -> bufB [N,64]

    // mean head
    k_gemm256<<<gG, 256>>>(bufB, mean_W, bufA, n, 64);
    k_prep<<<gW, 256>>>(bufA, mean_asrc, mean_adst, n);
    k_gat_agg<2><<<gW, 256>>>(bufA, mean_b, am, z_mean, n);

    // std head
    k_gemm256<<<gG, 256>>>(bufB, std_W, bufC, n, 64);
    k_prep<<<gW, 256>>>(bufC, std_asrc, std_adst, n);
    k_gat_agg<2><<<gW, 256>>>(bufC, std_b, as_, z_std, n);
}

// round 3
// speedup vs baseline: 1.2840x; 1.2840x over previous
#include <cuda_runtime.h>

#define MAXN 20000
#define MAXE 320000
#define MAXEP (MAXN + MAXE)

// ---------------- scratch (no allocs allowed) ----------------
__device__ int   g_deg[MAXN];
__device__ int   g_row[MAXN + 1];
__device__ int   g_cur[MAXN];
__device__ int   g_eid[MAXEP];
__device__ int   g_src[MAXEP];
__device__ float g_dis[MAXN];
__device__ __align__(16) float g_als[MAXN * 4];
__device__ __align__(16) float g_ald[MAXN * 4];
__device__ __align__(16) float g_als2[MAXN * 4];
__device__ __align__(16) float g_ald2[MAXN * 4];
__device__ __align__(16) float g_bufA[MAXN * 256];
__device__ __align__(16) float g_bufB[MAXN * 256];
__device__ __align__(16) float g_bufC[MAXN * 256];

// ---------------- CSR build ----------------
__global__ void k_zero(int n) {
    int i = blockIdx.x * blockDim.x + threadIdx.x;
    if (i < n) g_deg[i] = 0;
}

__global__ void k_count(const int* __restrict__ ei, int E, int EP) {
    int i = blockIdx.x * blockDim.x + threadIdx.x;
    if (i < EP) {
        int d = (i < E) ? ei[E + i] : (i - E);
        atomicAdd(&g_deg[d], 1);
    }
}

// single-block inclusive scan over N
__global__ void k_scan(int n) {
    __shared__ int sh[1024];
    __shared__ int carry_s;
    int tid = threadIdx.x;
    if (tid == 0) { carry_s = 0; g_row[0] = 0; }
    __syncthreads();
    for (int base = 0; base < n; base += 1024) {
        int i = base + tid;
        int v = (i < n) ? g_deg[i] : 0;
        sh[tid] = v;
        __syncthreads();
        for (int off = 1; off < 1024; off <<= 1) {
            int t = (tid >= off) ? sh[tid - off] : 0;
            __syncthreads();
            sh[tid] += t;
            __syncthreads();
        }
        int incl = sh[tid];
        int c = carry_s;
        if (i < n) {
            g_row[i + 1] = c + incl;
            g_cur[i]     = c + incl - v;
            g_dis[i]     = rsqrtf((float)v);
        }
        __syncthreads();
        if (tid == 1023) carry_s = c + incl;
        __syncthreads();
    }
}

__global__ void k_scatter(const int* __restrict__ ei, int E, int EP) {
    int i = blockIdx.x * blockDim.x + threadIdx.x;
    if (i < EP) {
        int d = (i < E) ? ei[E + i] : (i - E);
        int pos = atomicAdd(&g_cur[d], 1);
        g_eid[pos] = i;
    }
}

// deterministic order: sort each row's edge ids ascending; fused src fill
__global__ void k_sort_fill(const int* __restrict__ ei, int E, int n) {
    int i = blockIdx.x * blockDim.x + threadIdx.x;
    if (i >= n) return;
    int r0 = g_row[i], r1 = g_row[i + 1];
    for (int a = r0 + 1; a < r1; a++) {
        int v = g_eid[a];
        int b = a - 1;
        while (b >= r0 && g_eid[b] > v) { g_eid[b + 1] = g_eid[b]; b--; }
        g_eid[b + 1] = v;
    }
    for (int e = r0; e < r1; e++) {
        int eid = g_eid[e];
        g_src[e] = (eid < E) ? ei[eid] : (eid - E);
    }
}

// ---------------- GEMMs ----------------
// C[M,256] = A[M,K] @ W[K,256]; DUAL=1 -> blockIdx.y selects (W0,C0)/(W1,C1)
template <int DUAL>
__global__ __launch_bounds__(256) void k_gemm256(const float* __restrict__ A,
                                                 const float* __restrict__ W0,
                                                 const float* __restrict__ W1,
                                                 float* __restrict__ C0,
                                                 float* __restrict__ C1,
                                                 int M, int K) {
    const float* W = (DUAL && blockIdx.y) ? W1 : W0;
    float*       C = (DUAL && blockIdx.y) ? C1 : C0;
    __shared__ float Ash[64][36];
    __shared__ float Wsh[32][256];
    int tid = threadIdx.x;
    int x = tid & 31, y = tid >> 5;
    int row0 = blockIdx.x * 64;
    float acc[8][8];
#pragma unroll
    for (int i = 0; i < 8; i++)
#pragma unroll
        for (int j = 0; j < 8; j++) acc[i][j] = 0.f;

    for (int k0 = 0; k0 < K; k0 += 32) {
#pragma unroll
        for (int t = 0; t < 2; t++) {
            int idx = tid + t * 256;
            int r = idx >> 3, kq = idx & 7;
            int grow = row0 + r;
            float4 v = make_float4(0.f, 0.f, 0.f, 0.f);
            if (grow < M) v = *(const float4*)(A + (size_t)grow * K + k0 + kq * 4);
            *(float4*)&Ash[r][kq * 4] = v;
        }
#pragma unroll
        for (int t = 0; t < 8; t++) {
            int idx = tid + t * 256;
            int kr = idx >> 6, cq = idx & 63;
            *(float4*)&Wsh[kr][cq * 4] = *(const float4*)(W + (size_t)(k0 + kr) * 256 + cq * 4);
        }
        __syncthreads();
#pragma unroll
        for (int k = 0; k < 32; k++) {
            float a[8];
#pragma unroll
            for (int i = 0; i < 8; i++) a[i] = Ash[y + 8 * i][k];
            float4 w0 = *(float4*)&Wsh[k][x * 4];
            float4 w1 = *(float4*)&Wsh[k][x * 4 + 128];
#pragma unroll
            for (int i = 0; i < 8; i++) {
                acc[i][0] += a[i] * w0.x; acc[i][1] += a[i] * w0.y;
                acc[i][2] += a[i] * w0.z; acc[i][3] += a[i] * w0.w;
                acc[i][4] += a[i] * w1.x; acc[i][5] += a[i] * w1.y;
                acc[i][6] += a[i] * w1.z; acc[i][7] += a[i] * w1.w;
            }
        }
        __syncthreads();
    }
#pragma unroll
    for (int i = 0; i < 8; i++) {
        int r = row0 + y + 8 * i;
        if (r < M) {
            *(float4*)(C + (size_t)r * 256 + x * 4) =
                make_float4(acc[i][0], acc[i][1], acc[i][2], acc[i][3]);
            *(float4*)(C + (size_t)r * 256 + x * 4 + 128) =
                make_float4(acc[i][4], acc[i][5], acc[i][6], acc[i][7]);
        }
    }
}

// C[M,64] = A[M,K] @ W[K,64]
__global__ __launch_bounds__(256) void k_gemm64(const float* __restrict__ A,
                                                const float* __restrict__ W,
                                                float* __restrict__ C, int M, int K) {
    __shared__ float Ash[64][36];
    __shared__ float Wsh[32][64];
    int tid = threadIdx.x;
    int x = tid & 15, y = tid >> 4;
    int row0 = blockIdx.x * 64;
    float acc[4][4];
#pragma unroll
    for (int i = 0; i < 4; i++)
#pragma unroll
        for (int j = 0; j < 4; j++) acc[i][j] = 0.f;

    for (int k0 = 0; k0 < K; k0 += 32) {
#pragma unroll
        for (int t = 0; t < 2; t++) {
            int idx = tid + t * 256;
            int r = idx >> 3, kq = idx & 7;
            int grow = row0 + r;
            float4 v = make_float4(0.f, 0.f, 0.f, 0.f);
            if (grow < M) v = *(const float4*)(A + (size_t)grow * K + k0 + kq * 4);
            *(float4*)&Ash[r][kq * 4] = v;
        }
#pragma unroll
        for (int t = 0; t < 2; t++) {
            int idx = tid + t * 256;
            int kr = idx >> 4, cq = idx & 15;
            *(float4*)&Wsh[kr][cq * 4] = *(const float4*)(W + (size_t)(k0 + kr) * 64 + cq * 4);
        }
        __syncthreads();
#pragma unroll
        for (int k = 0; k < 32; k++) {
            float a[4];
#pragma unroll
            for (int i = 0; i < 4; i++) a[i] = Ash[y + 16 * i][k];
            float4 w = *(float4*)&Wsh[k][x * 4];
#pragma unroll
            for (int i = 0; i < 4; i++) {
                acc[i][0] += a[i] * w.x; acc[i][1] += a[i] * w.y;
                acc[i][2] += a[i] * w.z; acc[i][3] += a[i] * w.w;
            }
        }
        __syncthreads();
    }
#pragma unroll
    for (int i = 0; i < 4; i++) {
        int r = row0 + y + 16 * i;
        if (r < M)
            *(float4*)(C + (size_t)r * 64 + x * 4) =
                make_float4(acc[i][0], acc[i][1], acc[i][2], acc[i][3]);
    }
}

// ---------------- GCN aggregate (warp per node) ----------------
__global__ void k_gcn_agg(const float* __restrict__ xw, const float* __restrict__ bias,
                          float* __restrict__ out, int n) {
    int w = (blockIdx.x * blockDim.x + threadIdx.x) >> 5;
    int lane = threadIdx.x & 31;
    if (w >= n) return;
    int r0 = g_row[w], r1 = g_row[w + 1];
    float acc0 = 0.f, acc1 = 0.f;
    int e = r0;
    for (; e + 2 <= r1; e += 2) {
        int s0 = g_src[e], s1 = g_src[e + 1];
        float c0 = g_dis[s0], c1 = g_dis[s1];
        const float* xs0 = xw + (size_t)s0 * 64;
        const float* xs1 = xw + (size_t)s1 * 64;
        acc0 += c0 * xs0[lane] + c1 * xs1[lane];
        acc1 += c0 * xs0[32 + lane] + c1 * xs1[32 + lane];
    }
    if (e < r1) {
        int s = g_src[e];
        float sc = g_dis[s];
        const float* xs = xw + (size_t)s * 64;
        acc0 += sc * xs[lane];
        acc1 += sc * xs[32 + lane];
    }
    float di = g_dis[w];
    out[(size_t)w * 64 + lane]      = fmaxf(di * acc0 + bias[lane], 0.f);
    out[(size_t)w * 64 + 32 + lane] = fmaxf(di * acc1 + bias[32 + lane], 0.f);
}

// ---------------- attention prep ----------------
__device__ __forceinline__ void prep_node(const float* __restrict__ xw,
                                          const float* __restrict__ asrc,
                                          const float* __restrict__ adst,
                                          float* __restrict__ als,
                                          float* __restrict__ ald,
                                          int w, int lane) {
    const float4* xv = (const float4*)(xw + (size_t)w * 256);
    float4 x0 = xv[lane * 2], x1 = xv[lane * 2 + 1];
    const float4* sv = (const float4*)asrc;
    const float4* dv = (const float4*)adst;
    float4 a0 = sv[lane * 2], a1 = sv[lane * 2 + 1];
    float4 b0 = dv[lane * 2], b1 = dv[lane * 2 + 1];
    float ss = x0.x * a0.x + x0.y * a0.y + x0.z * a0.z + x0.w * a0.w
             + x1.x * a1.x + x1.y * a1.y + x1.z * a1.z + x1.w * a1.w;
    float dd = x0.x * b0.x + x0.y * b0.y + x0.z * b0.z + x0.w * b0.w
             + x1.x * b1.x + x1.y * b1.y + x1.z * b1.z + x1.w * b1.w;
#pragma unroll
    for (int d = 4; d; d >>= 1) {
        ss += __shfl_down_sync(0xffffffffu, ss, d);
        dd += __shfl_down_sync(0xffffffffu, dd, d);
    }
    if ((lane & 7) == 0) {
        int h = lane >> 3;
        als[(size_t)w * 4 + h] = ss;
        ald[(size_t)w * 4 + h] = dd;
    }
}

__global__ void k_prep(const float* __restrict__ xw, const float* __restrict__ asrc,
                       const float* __restrict__ adst, float* __restrict__ als,
                       float* __restrict__ ald, int n) {
    int w = (blockIdx.x * blockDim.x + threadIdx.x) >> 5;
    int lane = threadIdx.x & 31;
    if (w >= n) return;
    prep_node(xw, asrc, adst, als, ald, w, lane);
}

__global__ void k_prep_dual(const float* __restrict__ xw0, const float* __restrict__ a0s,
                            const float* __restrict__ a0d, float* __restrict__ als0,
                            float* __restrict__ ald0,
                            const float* __restrict__ xw1, const float* __restrict__ a1s,
                            const float* __restrict__ a1d, float* __restrict__ als1,
                            float* __restrict__ ald1, int n) {
    int w = (blockIdx.x * blockDim.x + threadIdx.x) >> 5;
    int lane = threadIdx.x & 31;
    if (w >= n) return;
    if (blockIdx.y == 0) prep_node(xw0, a0s, a0d, als0, ald0, w, lane);
    else                 prep_node(xw1, a1s, a1d, als1, ald1, w, lane);
}

// ---------------- GAT aggregate (warp per node, all 4 heads) ----------------
// MODE 0: concat(256)+bias+relu ; MODE 1: head-mean+bias+relu ; MODE 2: head-mean+bias
template <int MODE>
__device__ __forceinline__ void gat_node(const float* __restrict__ xw,
                                         const float* __restrict__ bias,
                                         const float* __restrict__ als,
                                         const float* __restrict__ ald,
                                         float* __restrict__ alpha,
                                         float* __restrict__ out,
                                         int w, int lane) {
    int r0 = g_row[w], r1 = g_row[w + 1];
    float4 ad = *(const float4*)&ald[(size_t)w * 4];

    // pass 1: exact max per head (lane-parallel over edges)
    float m0 = -3e38f, m1 = -3e38f, m2 = -3e38f, m3 = -3e38f;
    for (int e = r0 + lane; e < r1; e += 32) {
        int s = g_src[e];
        float4 as4 = *(const float4*)&als[(size_t)s * 4];
        float v0 = as4.x + ad.x; v0 = v0 > 0.f ? v0 : 0.2f * v0;
        float v1 = as4.y + ad.y; v1 = v1 > 0.f ? v1 : 0.2f * v1;
        float v2 = as4.z + ad.z; v2 = v2 > 0.f ? v2 : 0.2f * v2;
        float v3 = as4.w + ad.w; v3 = v3 > 0.f ? v3 : 0.2f * v3;
        m0 = fmaxf(m0, v0); m1 = fmaxf(m1, v1); m2 = fmaxf(m2, v2); m3 = fmaxf(m3, v3);
    }
#pragma unroll
    for (int d = 16; d; d >>= 1) {
        m0 = fmaxf(m0, __shfl_xor_sync(0xffffffffu, m0, d));
        m1 = fmaxf(m1, __shfl_xor_sync(0xffffffffu, m1, d));
        m2 = fmaxf(m2, __shfl_xor_sync(0xffffffffu, m2, d));
        m3 = fmaxf(m3, __shfl_xor_sync(0xffffffffu, m3, d));
    }

    // pass 2: sum of exp; stash unnormalized p in alpha output slot
    float s0 = 0.f, s1 = 0.f, s2 = 0.f, s3 = 0.f;
    for (int e = r0 + lane; e < r1; e += 32) {
        int eid = g_eid[e];
        int s = g_src[e];
        float4 as4 = *(const float4*)&als[(size_t)s * 4];
        float v0 = as4.x + ad.x; v0 = v0 > 0.f ? v0 : 0.2f * v0;
        float v1 = as4.y + ad.y; v1 = v1 > 0.f ? v1 : 0.2f * v1;
        float v2 = as4.z + ad.z; v2 = v2 > 0.f ? v2 : 0.2f * v2;
        float v3 = as4.w + ad.w; v3 = v3 > 0.f ? v3 : 0.2f * v3;
        float p0 = __expf(v0 - m0), p1 = __expf(v1 - m1);
        float p2 = __expf(v2 - m2), p3 = __expf(v3 - m3);
        s0 += p0; s1 += p1; s2 += p2; s3 += p3;
        *(float4*)&alpha[(size_t)eid * 4] = make_float4(p0, p1, p2, p3);
    }
#pragma unroll
    for (int d = 16; d; d >>= 1) {
        s0 += __shfl_xor_sync(0xffffffffu, s0, d);
        s1 += __shfl_xor_sync(0xffffffffu, s1, d);
        s2 += __shfl_xor_sync(0xffffffffu, s2, d);
        s3 += __shfl_xor_sync(0xffffffffu, s3, d);
    }
    float i0 = 1.f / (s0 + 1e-16f), i1 = 1.f / (s1 + 1e-16f);
    float i2 = 1.f / (s2 + 1e-16f), i3 = 1.f / (s3 + 1e-16f);
    __syncwarp();

    // pass 3a: normalize alpha in place (lane-parallel, clean float4 stores)
    for (int e = r0 + lane; e < r1; e += 32) {
        int eid = g_eid[e];
        float4 p = *(const float4*)&alpha[(size_t)eid * 4];
        *(float4*)&alpha[(size_t)eid * 4] =
            make_float4(p.x * i0, p.y * i1, p.z * i2, p.w * i3);
    }
    __syncwarp();

    // pass 3b: aggregate 256 channels, unroll 2 for MLP
    float acc[8] = {0.f, 0.f, 0.f, 0.f, 0.f, 0.f, 0.f, 0.f};
    int e = r0;
    for (; e + 2 <= r1; e += 2) {
        int eidA = g_eid[e],     sA = g_src[e];
        int eidB = g_eid[e + 1], sB = g_src[e + 1];
        float4 pA = *(const float4*)&alpha[(size_t)eidA * 4];
        float4 pB = *(const float4*)&alpha[(size_t)eidB * 4];
        const float* xA = xw + (size_t)sA * 256;
        const float* xB = xw + (size_t)sB * 256;
        acc[0] += pA.x * xA[lane]       + pB.x * xB[lane];
        acc[1] += pA.x * xA[32 + lane]  + pB.x * xB[32 + lane];
        acc[2] += pA.y * xA[64 + lane]  + pB.y * xB[64 + lane];
        acc[3] += pA.y * xA[96 + lane]  + pB.y * xB[96 + lane];
        acc[4] += pA.z * xA[128 + lane] + pB.z * xB[128 + lane];
        acc[5] += pA.z * xA[160 + lane] + pB.z * xB[160 + lane];
        acc[6] += pA.w * xA[192 + lane] + pB.w * xB[192 + lane];
        acc[7] += pA.w * xA[224 + lane] + pB.w * xB[224 + lane];
    }
    if (e < r1) {
        int eid = g_eid[e], s = g_src[e];
        float4 p = *(const float4*)&alpha[(size_t)eid * 4];
        const float* xs = xw + (size_t)s * 256;
        acc[0] += p.x * xs[lane];        acc[1] += p.x * xs[32 + lane];
        acc[2] += p.y * xs[64 + lane];   acc[3] += p.y * xs[96 + lane];
        acc[4] += p.z * xs[128 + lane];  acc[5] += p.z * xs[160 + lane];
        acc[6] += p.w * xs[192 + lane];  acc[7] += p.w * xs[224 + lane];
    }

    if (MODE == 0) {
#pragma unroll
        for (int k = 0; k < 8; k++) {
            int c = k * 32 + lane;
            out[(size_t)w * 256 + c] = fmaxf(acc[k] + bias[c], 0.f);
        }
    } else {
        float u0 = (acc[0] + acc[2] + acc[4] + acc[6]) * 0.25f + bias[lane];
        float u1 = (acc[1] + acc[3] + acc[5] + acc[7]) * 0.25f + bias[32 + lane];
        if (MODE == 1) { u0 = fmaxf(u0, 0.f); u1 = fmaxf(u1, 0.f); }
        out[(size_t)w * 64 + lane]      = u0;
        out[(size_t)w * 64 + 32 + lane] = u1;
    }
}

template <int MODE>
__global__ void k_gat_agg(const float* __restrict__ xw, const float* __restrict__ bias,
                          const float* __restrict__ als, const float* __restrict__ ald,
                          float* __restrict__ alpha, float* __restrict__ out, int n) {
    int w = (blockIdx.x * blockDim.x + threadIdx.x) >> 5;
    int lane = threadIdx.x & 31;
    if (w >= n) return;
    gat_node<MODE>(xw, bias, als, ald, alpha, out, w, lane);
}

__global__ void k_gat_agg_dual(const float* __restrict__ xw0, const float* __restrict__ b0,
                               const float* __restrict__ als0, const float* __restrict__ ald0,
                               float* __restrict__ alpha0, float* __restrict__ out0,
                               const float* __restrict__ xw1, const float* __restrict__ b1,
                               const float* __restrict__ als1, const float* __restrict__ ald1,
                               float* __restrict__ alpha1, float* __restrict__ out1, int n) {
    int w = (blockIdx.x * blockDim.x + threadIdx.x) >> 5;
    int lane = threadIdx.x & 31;
    if (w >= n) return;
    if (blockIdx.y == 0) gat_node<2>(xw0, b0, als0, ald0, alpha0, out0, w, lane);
    else                 gat_node<2>(xw1, b1, als1, ald1, alpha1, out1, w, lane);
}

// ---------------- host ----------------
extern "C" void kernel_launch(void* const* d_in, const int* in_sizes, int n_in,
                              void* d_out, int out_size) {
    int n  = in_sizes[0] / 128;
    int E  = in_sizes[1] / 2;
    int EP = E + n;

    const float* x         = (const float*)d_in[0];
    const int*   ei        = (const int*)d_in[1];
    const float* gcn_W     = (const float*)d_in[2];
    const float* gcn_b     = (const float*)d_in[3];
    const float* gat1_W    = (const float*)d_in[4];
    const float* gat1_asrc = (const float*)d_in[5];
    const float* gat1_adst = (const float*)d_in[6];
    const float* gat1_b    = (const float*)d_in[7];
    const float* gat2_W    = (const float*)d_in[8];
    const float* gat2_asrc = (const float*)d_in[9];
    const float* gat2_adst = (const float*)d_in[10];
    const float* gat2_b    = (const float*)d_in[11];
    const float* mean_W    = (const float*)d_in[12];
    const float* mean_asrc = (const float*)d_in[13];
    const float* mean_adst = (const float*)d_in[14];
    const float* mean_b    = (const float*)d_in[15];
    const float* std_W     = (const float*)d_in[16];
    const float* std_asrc  = (const float*)d_in[17];
    const float* std_adst  = (const float*)d_in[18];
    const float* std_b     = (const float*)d_in[19];

    float* out    = (float*)d_out;
    float* z_mean = out;
    float* z_std  = out + (size_t)n * 64;
    float* a1     = out + (size_t)2 * n * 64;
    float* a2     = a1 + (size_t)EP * 4;
    float* am     = a2 + (size_t)EP * 4;
    float* as_    = am + (size_t)EP * 4;

    float *bufA, *bufB, *bufC, *als, *ald, *als2, *ald2;
    cudaGetSymbolAddress((void**)&bufA, g_bufA);
    cudaGetSymbolAddress((void**)&bufB, g_bufB);
    cudaGetSymbolAddress((void**)&bufC, g_bufC);
    cudaGetSymbolAddress((void**)&als,  g_als);
    cudaGetSymbolAddress((void**)&ald,  g_ald);
    cudaGetSymbolAddress((void**)&als2, g_als2);
    cudaGetSymbolAddress((void**)&ald2, g_ald2);

    int gN  = (n + 255) / 256;
    int gEP = (EP + 255) / 256;
    int gW  = (n + 7) / 8;        // warp-per-node kernels, 256 threads
    int gG  = (n + 63) / 64;      // GEMM row blocks

    // CSR build (deterministic: rows sorted by edge id)
    k_zero<<<gN, 256>>>(n);
    k_count<<<gEP, 256>>>(ei, E, EP);
    k_scan<<<1, 1024>>>(n);
    k_scatter<<<gEP, 256>>>(ei, E, EP);
    k_sort_fill<<<(n + 127) / 128, 128>>>(ei, E, n);

    // layer 0: GCN
    k_gemm64<<<gG, 256>>>(x, gcn_W, bufA, n, 128);
    k_gcn_agg<<<gW, 256>>>(bufA, gcn_b, bufB, n);                 // h0 -> bufB [N,64]

    // layer 1: GAT concat
    k_gemm256<0><<<gG, 256>>>(bufB, gat1_W, nullptr, bufA, nullptr, n, 64);
    k_prep<<<gW, 256>>>(bufA, gat1_asrc, gat1_adst, als, ald, n);
    k_gat_agg<0><<<gW, 256>>>(bufA, gat1_b, als, ald, a1, bufC, n);   // h1 -> bufC [N,256]

    // layer 2: GAT mean + relu
    k_gemm256<0><<<gG, 256>>>(bufC, gat2_W, nullptr, bufA, nullptr, n, 256);
    k_prep<<<gW, 256>>>(bufA, gat2_asrc, gat2_adst, als, ald, n);
    k_gat_agg<1><<<gW, 256>>>(bufA, gat2_b, als, ald, a2, bufB, n);   // h2 -> bufB [N,64]

    // fused mean + std heads (independent -> batched via blockIdx.y)
    dim3 gridG2(gG, 2), gridW2(gW, 2);
    k_gemm256<1><<<gridG2, 256>>>(bufB, mean_W, std_W, bufA, bufC, n, 64);
    k_prep_dual<<<gridW2, 256>>>(bufA, mean_asrc, mean_adst, als, ald,
                                 bufC, std_asrc,  std_adst,  als2, ald2, n);
    k_gat_agg_dual<<<gridW2, 256>>>(bufA, mean_b, als, ald, am,  z_mean,
                                    bufC, std_b,  als2, ald2, as_, z_std, n);
}